// round 15
// baseline (speedup 1.0000x reference)
#include <cuda_runtime.h>
#include <cuda_fp16.h>
#include <math.h>
#include <stdint.h>

#define HW    16384
#define WIDTH 128
#define NB    8
#define CQKV  192

// ---------------- scratch (static device allocations; no cudaMalloc) --------
__device__ float    g_qkv[NB * CQKV * HW];    // 100.7 MB
__device__ float    g_d  [NB * CQKV * HW];    // 100.7 MB
__device__ uint32_t g_xh [NB * HW * 128];     // x packed fp16 pairs, PIXEL-major
__device__ uint32_t g_oh [NB * HW * 64];      // o packed fp16 pairs, PIXEL-major
__device__ uint32_t g_wqh[CQKV * 128];        // qkv weights packed [m][kp]
__device__ uint32_t g_wfh[256 * 64];          // ffn weights packed [m][kp]
__device__ float    g_kvp[NB * 16 * 8 * 72];

// ---------------- fp16 helpers ----------------------------------------------
__device__ __forceinline__ uint32_t hpack(float a, float b) {
    __half2 t = __floats2half2_rn(a, b);      // .x = a (low), .y = b (high)
    return *reinterpret_cast<uint32_t*>(&t);
}
__device__ __forceinline__ void mma_fp16(float c[4], const uint32_t a[4], const uint32_t b[2]) {
    asm volatile(
        "mma.sync.aligned.m16n8k16.row.col.f32.f16.f16.f32 "
        "{%0,%1,%2,%3}, {%4,%5,%6,%7}, {%8,%9}, {%0,%1,%2,%3};\n"
        : "+f"(c[0]), "+f"(c[1]), "+f"(c[2]), "+f"(c[3])
        : "r"(a[0]), "r"(a[1]), "r"(a[2]), "r"(a[3]), "r"(b[0]), "r"(b[1]));
}
__device__ __forceinline__ void ldm_x4(uint32_t r[4], uint32_t addr) {
    asm volatile("ldmatrix.sync.aligned.m8n8.x4.shared.b16 {%0,%1,%2,%3}, [%4];"
        : "=r"(r[0]), "=r"(r[1]), "=r"(r[2]), "=r"(r[3]) : "r"(addr));
}
__device__ __forceinline__ uint32_t smem_u32(const void* p) {
    uint32_t a;
    asm("{ .reg .u64 t; cvta.to.shared.u64 t, %1; cvt.u32.u64 %0, t; }" : "=r"(a) : "l"(p));
    return a;
}
__device__ __forceinline__ void cpa16(uint32_t dst, const void* src) {
    asm volatile("cp.async.cg.shared.global [%0], [%1], 16;\n" :: "r"(dst), "l"(src));
}
#define CPA_COMMIT() asm volatile("cp.async.commit_group;\n" ::: "memory")
#define CPA_WAIT0()  asm volatile("cp.async.wait_group 0;\n" ::: "memory")

// ---------------- convert kernels -------------------------------------------
__global__ void wcvt_kernel(const float* __restrict__ W,
                            uint32_t* __restrict__ WH, int npairs)
{
    int i = blockIdx.x * 256 + threadIdx.x;
    if (i >= npairs) return;
    WH[i] = hpack(W[2 * i], W[2 * i + 1]);
}

// X [b][256][HW] -> pixel-major packed array XH [b][n][kp], kp = 0..127
// 32-pixel tiles transposed through smem.
__global__ void __launch_bounds__(256)
xcvt_kernel(const float* __restrict__ X, uint32_t* __restrict__ XH)
{
    __shared__ uint32_t tile[32 * 133];
    const int b  = blockIdx.y;
    const int n0 = blockIdx.x * 32;
    const float* Xb = X + (size_t)b * 256 * HW;
    uint32_t*   XHb = XH + ((size_t)b * HW + n0) * 128;

    #pragma unroll
    for (int i = 0; i < 16; i++) {
        int lin = threadIdx.x + i * 256;
        int n = lin & 31, kp = lin >> 5;
        float a = Xb[(size_t)(2 * kp) * HW + n0 + n];
        float c = Xb[(size_t)(2 * kp + 1) * HW + n0 + n];
        tile[n * 133 + kp] = hpack(a, c);
    }
    __syncthreads();

    #pragma unroll
    for (int i = 0; i < 4; i++) {
        int lin = threadIdx.x + i * 256;
        int n = lin >> 5, c4 = (lin & 31) * 4;
        uint4 w = make_uint4(tile[n * 133 + c4],     tile[n * 133 + c4 + 1],
                             tile[n * 133 + c4 + 2], tile[n * 133 + c4 + 3]);
        *(uint4*)&XHb[(size_t)n * 128 + c4] = w;
    }
}

// ============ fp16 HMMA GEMM w/ ldmatrix fragments ==========================
// C[b](M x HW) = W(M x KTOT) * X[b](KTOT x HW)
// Block 64(M) x 128(N), 128 threads (4 warps 2x2, 32x64 warp tiles).
// A smem [64 rows][20] row-major; B smem [128 cols][20] col-major (both
// ldmatrix-ready, conflict-free). Activations are pixel-major in gmem.
// 2-stage cp.async pipeline, race-free order (wait -> sync -> prefetch).
// MMA operand values and order identical to R13/R14 (rel_err preserved).
template <int KTOT, int MODE>
__global__ void __launch_bounds__(128)
hgemm(const uint32_t* __restrict__ AH,
      const uint32_t* __restrict__ BHg,
      float* __restrict__ C, int M,
      const float* __restrict__ gamma, const float* __restrict__ beta,
      const float* __restrict__ mean,  const float* __restrict__ var)
{
    constexpr int KP   = KTOT / 2;
    constexpr int NKIT = KTOT / 32;
    constexpr int AW   = 64 * 20;          // 1280 words
    constexpr int BW   = 128 * 20;         // 2560 words
    constexpr int SWRD = AW + BW;          // 3840 words per stage

    __shared__ uint32_t sm[8448];          // max(2*SWRD=7680, epi 64*132=8448)
    const uint32_t smb = smem_u32(sm);

    const int tid  = threadIdx.x;
    const int lane = tid & 31;
    const int warp = tid >> 5;
    const int wm   = warp >> 1;            // 0..1 -> 32 rows
    const int wn   = warp & 1;             // 0..1 -> 64 cols
    const int g    = lane >> 2;
    const int tg   = lane & 3;
    const int l15  = lane & 15;
    const int lq   = (lane >> 4) * 4;

    const int m0 = blockIdx.y * 64;
    const int n0 = blockIdx.x * 128;
    const uint32_t* Bn = BHg + (size_t)blockIdx.z * HW * KP;
    float*          Cb = C   + (size_t)blockIdx.z * M * HW;

    // ldmatrix lane-address components (byte offsets within region)
    const uint32_t aoff = (uint32_t)((wm * 32 + l15) * 20 + lq) * 4;
    const uint32_t boff = (uint32_t)((wn * 64 + l15) * 20 + lq) * 4;

    // loader roles
    const int arow = tid >> 1, aq = (tid & 1) * 8;   // A: 64 rows, 8-word halves

    auto load_chunk = [&](int it, int stage) {
        const uint32_t s0 = smb + (uint32_t)stage * SWRD * 4;
        const uint32_t* srcA = AH + (size_t)(m0 + arow) * KP + it * 16 + aq;
        uint32_t dA = s0 + (uint32_t)(arow * 20 + aq) * 4;
        cpa16(dA,      srcA);
        cpa16(dA + 16, srcA + 4);
        // B: col t, 16 kp words contiguous in gmem (pixel-major)
        const uint32_t* srcB = Bn + (size_t)(n0 + tid) * KP + it * 16;
        uint32_t dB = s0 + (uint32_t)(AW + tid * 20) * 4;
        #pragma unroll
        for (int q = 0; q < 4; q++) cpa16(dB + q * 16, srcB + q * 4);
    };

    load_chunk(0, 0); CPA_COMMIT();

    float c[2][8][4] = {};

    for (int it = 0; it < NKIT; it++) {
        CPA_WAIT0();
        __syncthreads();
        if (it + 1 < NKIT) { load_chunk(it + 1, (it + 1) & 1); CPA_COMMIT(); }

        const uint32_t sA = smb + (uint32_t)(it & 1) * SWRD * 4;
        const uint32_t sB = sA + AW * 4;

        #pragma unroll
        for (int ks = 0; ks < 2; ks++) {
            const uint32_t kb = (uint32_t)(ks * 8) * 4;
            uint32_t ah[2][4], bf[4][4];
            ldm_x4(ah[0], sA + aoff + kb);
            ldm_x4(ah[1], sA + aoff + 1280 + kb);
            #pragma unroll
            for (int j = 0; j < 4; j++)
                ldm_x4(bf[j], sB + boff + (uint32_t)j * 1280 + kb);
            // bf[j] = {bh[2j][0], bh[2j+1][0], bh[2j][1], bh[2j+1][1]}
            #pragma unroll
            for (int nt = 0; nt < 8; nt++) {
                uint32_t bb[2] = { bf[nt >> 1][nt & 1], bf[nt >> 1][2 + (nt & 1)] };
                #pragma unroll
                for (int mt = 0; mt < 2; mt++) mma_fp16(c[mt][nt], ah[mt], bb);
            }
        }
        __syncthreads();
    }

    // ---- epilogue: stage C tile in smem (stride 132), coalesced writeout ----
    float* Cs = (float*)sm;
    #pragma unroll
    for (int mt = 0; mt < 2; mt++)
        #pragma unroll
        for (int nt = 0; nt < 8; nt++) {
            int r   = wm * 32 + mt * 16 + g;
            int col = wn * 64 + nt * 8 + tg * 2;
            Cs[r * 132 + col]           = c[mt][nt][0];
            Cs[r * 132 + col + 1]       = c[mt][nt][1];
            Cs[(r + 8) * 132 + col]     = c[mt][nt][2];
            Cs[(r + 8) * 132 + col + 1] = c[mt][nt][3];
        }
    __syncthreads();

    #pragma unroll 8
    for (int i = tid; i < 8192; i += 128) {
        int r = i >> 7, n = i & 127;
        float v = Cs[r * 132 + n];
        if (MODE == 1) {
            int m = m0 + r;
            float sc = __ldg(&gamma[m]) * rsqrtf(__ldg(&var[m]) + 1e-5f);
            v = v * sc + __ldg(&beta[m]) - __ldg(&mean[m]) * sc;
        }
        Cb[(size_t)(m0 + r) * HW + n0 + n] = v;
    }
}

// ------- fused p-mix + depthwise 3x3 (SAME), 4 output rows per block --------
__global__ void __launch_bounds__(256)
pdw_kernel(const float* __restrict__ QKV,
           const float* __restrict__ Wp,
           const float* __restrict__ Wd,
           float* __restrict__ D)
{
    __shared__ float sin[8][6][WIDTH];
    __shared__ float sp [8][6][WIDTH];

    const int b  = blockIdx.z;
    const int gr = blockIdx.y;
    const int h0 = blockIdx.x * 4;
    const int tid = threadIdx.x;
    const float* src = QKV + ((size_t)b * CQKV + gr * 8) * HW;

    #pragma unroll
    for (int i = 0; i < 24; i++) {
        int lin = tid + i * 256;
        int ch = lin / 768, rem = lin - ch * 768;
        int rs = rem >> 7, col = rem & 127;
        int row = h0 - 1 + rs;
        sin[ch][rs][col] = ((unsigned)row < (unsigned)WIDTH)
                           ? src[ch * HW + row * WIDTH + col] : 0.f;
    }
    __syncthreads();

    #pragma unroll
    for (int i = 0; i < 24; i++) {
        int lin = tid + i * 256;
        int oc = lin / 768, rem = lin - oc * 768;
        int rs = rem >> 7, col = rem & 127;
        float s = 0.f;
        #pragma unroll
        for (int ic = 0; ic < 8; ic++)
            s += __ldg(&Wp[gr * 64 + oc * 8 + ic]) * sin[ic][rs][col];
        sp[oc][rs][col] = s;
    }
    __syncthreads();

    #pragma unroll
    for (int i = 0; i < 16; i++) {
        int lin = tid + i * 256;
        int oc = lin >> 9, hr = (lin >> 7) & 3, col = lin & 127;
        int c = gr * 8 + oc;
        float s = 0.f;
        #pragma unroll
        for (int ky = 0; ky < 3; ky++) {
            float w0 = __ldg(&Wd[c * 9 + ky * 3 + 0]);
            float w1 = __ldg(&Wd[c * 9 + ky * 3 + 1]);
            float w2 = __ldg(&Wd[c * 9 + ky * 3 + 2]);
            const float* row = sp[oc][hr + ky];
            if (col > 0)   s += w0 * row[col - 1];
            s += w1 * row[col];
            if (col < 127) s += w2 * row[col + 1];
        }
        D[((size_t)b * CQKV + c) * HW + (h0 + hr) * WIDTH + col] = s;
    }
}

// ---------------- kv partial sums (float4 loads) -----------------------------
__global__ void __launch_bounds__(256)
kv_kernel(const float* __restrict__ QKV,
          const float* __restrict__ D,
          float* __restrict__ kvp)
{
    const int b = blockIdx.z, G = blockIdx.y, chunk = blockIdx.x;
    const int tid = threadIdx.x;
    const float* base = (G < 8) ? QKV + ((size_t)b * CQKV + G * 24) * HW
                                : D   + ((size_t)b * CQKV + (G - 8) * 24) * HW;
    float acc[72];
    #pragma unroll
    for (int i = 0; i < 72; i++) acc[i] = 0.f;

    #pragma unroll
    for (int it = 0; it < 2; it++) {
        int n = chunk * 2048 + it * 1024 + tid * 4;
        float4 kr[8], vr[8];
        #pragma unroll
        for (int d = 0; d < 8; d++) {
            float4 t = *(const float4*)&base[(8 + d) * HW + n];
            kr[d].x = fmaxf(t.x, 0.f); kr[d].y = fmaxf(t.y, 0.f);
            kr[d].z = fmaxf(t.z, 0.f); kr[d].w = fmaxf(t.w, 0.f);
        }
        #pragma unroll
        for (int e = 0; e < 8; e++) vr[e] = *(const float4*)&base[(16 + e) * HW + n];
        #pragma unroll
        for (int d = 0; d < 8; d++) {
            #pragma unroll
            for (int e = 0; e < 8; e++)
                acc[d * 9 + e] += kr[d].x * vr[e].x + kr[d].y * vr[e].y
                                + kr[d].z * vr[e].z + kr[d].w * vr[e].w;
            acc[d * 9 + 8] += kr[d].x + kr[d].y + kr[d].z + kr[d].w;
        }
    }

    __shared__ float red[8][72];
    const int lane = tid & 31, warp = tid >> 5;
    #pragma unroll
    for (int i = 0; i < 72; i++) {
        float v = acc[i];
        #pragma unroll
        for (int off = 16; off; off >>= 1) v += __shfl_down_sync(0xffffffffu, v, off);
        if (lane == 0) red[warp][i] = v;
    }
    __syncthreads();
    for (int i = tid; i < 72; i += 256) {
        float s = 0.f;
        #pragma unroll
        for (int w2 = 0; w2 < 8; w2++) s += red[w2][i];
        kvp[((size_t)(b * 16 + G) * 8 + chunk) * 72 + i] = s;
    }
}

// ------- o = normalize(relu(q)@kv), 2 px/thread, pixel-major fp16 output ----
__global__ void __launch_bounds__(256)
o_kernel(const float* __restrict__ QKV,
         const float* __restrict__ D,
         const float* __restrict__ kvp,
         uint32_t* __restrict__ OH)
{
    const int b = blockIdx.y;
    __shared__ float skv[16 * 72];
    for (int i = threadIdx.x; i < 16 * 72; i += 256) {
        float s = 0.f;
        #pragma unroll
        for (int c = 0; c < 8; c++)
            s += kvp[((size_t)(b * 16 + (i / 72)) * 8 + c) * 72 + (i % 72)];
        skv[i] = s;
    }
    __syncthreads();

    const int n = blockIdx.x * 512 + threadIdx.x * 2;
    uint32_t* OHb = OH + (size_t)b * HW * 64;
    #pragma unroll
    for (int G = 0; G < 16; G++) {
        const float* base = (G < 8) ? QKV + ((size_t)b * CQKV + G * 24) * HW
                                    : D   + ((size_t)b * CQKV + (G - 8) * 24) * HW;
        float2 num[8];
        #pragma unroll
        for (int j = 0; j < 8; j++) num[j] = make_float2(0.f, 0.f);
        float2 den = make_float2(0.f, 0.f);
        #pragma unroll
        for (int d = 0; d < 8; d++) {
            float2 t = *(const float2*)&base[d * HW + n];
            float qx = fmaxf(t.x, 0.f), qy = fmaxf(t.y, 0.f);
            #pragma unroll
            for (int j = 0; j < 8; j++) {
                float w = skv[G * 72 + d * 9 + j];
                num[j].x += qx * w;
                num[j].y += qy * w;
            }
            float w8 = skv[G * 72 + d * 9 + 8];
            den.x += qx * w8;
            den.y += qy * w8;
        }
        float invx = 1.f / (den.x + 1e-15f);
        float invy = 1.f / (den.y + 1e-15f);
        uint4 wx, wy;
        wx.x = hpack(num[0].x * invx, num[1].x * invx);
        wx.y = hpack(num[2].x * invx, num[3].x * invx);
        wx.z = hpack(num[4].x * invx, num[5].x * invx);
        wx.w = hpack(num[6].x * invx, num[7].x * invx);
        wy.x = hpack(num[0].y * invy, num[1].y * invy);
        wy.y = hpack(num[2].y * invy, num[3].y * invy);
        wy.z = hpack(num[4].y * invy, num[5].y * invy);
        wy.w = hpack(num[6].y * invy, num[7].y * invy);
        *(uint4*)&OHb[(size_t)n * 64 + G * 4]       = wx;
        *(uint4*)&OHb[(size_t)(n + 1) * 64 + G * 4] = wy;
    }
}

// ---------------- launch --------------------------------------------------
extern "C" void kernel_launch(void* const* d_in, const int* in_sizes, int n_in,
                              void* d_out, int out_size)
{
    const float* x     = (const float*)d_in[0];
    const float* W_qkv = (const float*)d_in[1];
    const float* W_p   = (const float*)d_in[2];
    const float* W_d   = (const float*)d_in[3];
    const float* W_ffn = (const float*)d_in[4];
    const float* gamma = (const float*)d_in[5];
    const float* beta  = (const float*)d_in[6];
    const float* mean  = (const float*)d_in[7];
    const float* var   = (const float*)d_in[8];
    float* out = (float*)d_out;

    float *qkv, *d, *kvp;
    uint32_t *xh, *oh, *wqh, *wfh;
    cudaGetSymbolAddress((void**)&qkv, g_qkv);
    cudaGetSymbolAddress((void**)&d,   g_d);
    cudaGetSymbolAddress((void**)&xh,  g_xh);
    cudaGetSymbolAddress((void**)&oh,  g_oh);
    cudaGetSymbolAddress((void**)&wqh, g_wqh);
    cudaGetSymbolAddress((void**)&wfh, g_wfh);
    cudaGetSymbolAddress((void**)&kvp, g_kvp);

    // 0) operand conversions (once per call)
    wcvt_kernel<<<(CQKV * 128 + 255) / 256, 256>>>(W_qkv, wqh, CQKV * 128);
    wcvt_kernel<<<(256 * 64 + 255) / 256, 256>>>(W_ffn, wfh, 256 * 64);
    xcvt_kernel<<<dim3(HW / 32, NB), 256>>>(x, xh);

    // 1) qkv = W_qkv @ x   (fp16 HMMA + ldmatrix)
    hgemm<256, 0><<<dim3(HW / 128, CQKV / 64, NB), 128>>>(
        wqh, xh, qkv, CQKV, nullptr, nullptr, nullptr, nullptr);

    // 2) d = depthwise3x3(blockdiag(W_p) @ qkv)
    pdw_kernel<<<dim3(WIDTH / 4, 24, NB), 256>>>(qkv, W_p, W_d, d);

    // 3) kv partial sums
    kv_kernel<<<dim3(8, 16, NB), 256>>>(qkv, d, kvp);

    // 4) o = normalize(relu(q) @ kv) -> pixel-major packed fp16
    o_kernel<<<dim3(HW / 512, NB), 256>>>(qkv, d, kvp, oh);

    // 5) out = BN(W_ffn @ o)
    hgemm<128, 1><<<dim3(HW / 128, 256 / 64, NB), 128>>>(
        wfh, oh, out, 256, gamma, beta, mean, var);
}

// round 16
// speedup vs baseline: 1.0257x; 1.0257x over previous
#include <cuda_runtime.h>
#include <cuda_fp16.h>
#include <math.h>
#include <stdint.h>

#define HW    16384
#define WIDTH 128
#define NB    8
#define CQKV  192

// ---------------- scratch (static device allocations; no cudaMalloc) --------
__device__ float    g_qkv[NB * CQKV * HW];    // 100.7 MB
__device__ float    g_d  [NB * CQKV * HW];    // 100.7 MB
__device__ uint32_t g_xh [NB * 128 * HW];     // x packed fp16-pair (67 MB)
__device__ uint32_t g_oh [NB * 64 * HW];      // o packed fp16-pair (33.5 MB)
__device__ uint32_t g_wqh[CQKV * 128];        // qkv weights packed
__device__ uint32_t g_wfh[256 * 64];          // ffn weights packed
__device__ float    g_kvp[NB * 16 * 8 * 72];

// ---------------- fp16 helpers ----------------------------------------------
__device__ __forceinline__ uint32_t hpack(float a, float b) {
    __half2 t = __floats2half2_rn(a, b);      // .x = a (low), .y = b (high)
    return *reinterpret_cast<uint32_t*>(&t);
}
__device__ __forceinline__ void mma_fp16(float c[4], const uint32_t a[4], const uint32_t b[2]) {
    asm volatile(
        "mma.sync.aligned.m16n8k16.row.col.f32.f16.f16.f32 "
        "{%0,%1,%2,%3}, {%4,%5,%6,%7}, {%8,%9}, {%0,%1,%2,%3};\n"
        : "+f"(c[0]), "+f"(c[1]), "+f"(c[2]), "+f"(c[3])
        : "r"(a[0]), "r"(a[1]), "r"(a[2]), "r"(a[3]), "r"(b[0]), "r"(b[1]));
}
__device__ __forceinline__ uint32_t smem_u32(const void* p) {
    uint32_t a;
    asm("{ .reg .u64 t; cvta.to.shared.u64 t, %1; cvt.u32.u64 %0, t; }" : "=r"(a) : "l"(p));
    return a;
}
__device__ __forceinline__ void cpa16(uint32_t dst, const void* src) {
    asm volatile("cp.async.cg.shared.global [%0], [%1], 16;\n" :: "r"(dst), "l"(src));
}
#define CPA_COMMIT() asm volatile("cp.async.commit_group;\n" ::: "memory")
#define CPA_WAIT2()  asm volatile("cp.async.wait_group 2;\n" ::: "memory")
#define CPA_WAIT1()  asm volatile("cp.async.wait_group 1;\n" ::: "memory")
#define CPA_WAIT0()  asm volatile("cp.async.wait_group 0;\n" ::: "memory")

// ---------------- convert kernels -------------------------------------------
__global__ void wcvt_kernel(const float* __restrict__ W,
                            uint32_t* __restrict__ WH, int npairs)
{
    int i = blockIdx.x * 256 + threadIdx.x;
    if (i >= npairs) return;
    WH[i] = hpack(W[2 * i], W[2 * i + 1]);
}

// X [b][K][HW] -> packed fp16 k-pair array [b][K/2][HW]
__global__ void xcvt_kernel(const float* __restrict__ X, uint32_t* __restrict__ XH)
{
    int idx = blockIdx.x * 256 + threadIdx.x;
    int n  = (idx & 4095) * 4;
    int t  = idx >> 12;                           // b*128 + kp
    const float4 a = *(const float4*)&X[(size_t)t * 2 * HW + n];
    const float4 b = *(const float4*)&X[(size_t)t * 2 * HW + HW + n];
    uint4 w;
    w.x = hpack(a.x, b.x);
    w.y = hpack(a.y, b.y);
    w.z = hpack(a.z, b.z);
    w.w = hpack(a.w, b.w);
    *(uint4*)&XH[(size_t)t * HW + n] = w;
}

// ============ fp16 single-pass HMMA GEMM, 64x128 block, 32x64 warp tiles ====
// C[b](M x HW) = W(M x KTOT) * X[b](KTOT x HW)
// 128 threads = 4 warps (2x2), k32 chunks, 3-stage cp.async pipeline.
// MODE 0: plain store. MODE 1: batchnorm affine on channel (row).
// (R10/R13/R14-measured best configuration — FROZEN.)
template <int KTOT, int MODE>
__global__ void __launch_bounds__(128)
hgemm(const uint32_t* __restrict__ AH,
      const uint32_t* __restrict__ BHg,
      float* __restrict__ C, int M,
      const float* __restrict__ gamma, const float* __restrict__ beta,
      const float* __restrict__ mean,  const float* __restrict__ var)
{
    constexpr int KP   = KTOT / 2;
    constexpr int NKIT = KTOT / 32;
    constexpr int SWRD = 3456;            // A[64][20]=1280 + B[16][136]=2176
    constexpr int NSTG = 3;

    __shared__ uint32_t sm[NSTG * SWRD];  // 41472 B
    const uint32_t smb = smem_u32(sm);

    const int tid  = threadIdx.x;
    const int lane = tid & 31;
    const int warp = tid >> 5;
    const int wm   = warp >> 1;           // 0..1 -> 32 rows
    const int wn   = warp & 1;            // 0..1 -> 64 cols
    const int g    = lane >> 2;
    const int tg   = lane & 3;

    const int m0 = blockIdx.y * 64;
    const int n0 = blockIdx.x * 128;
    const uint32_t* Bh = BHg + (size_t)blockIdx.z * KP * HW;
    float*          Cb = C   + (size_t)blockIdx.z * M * HW;

    // loader roles
    const int arow = tid >> 1, aq = (tid & 1) * 8;    // A: 64 rows, 8-word halves
    const int brow = tid >> 3, bs = (tid & 7) * 16;   // B: 16 kp-rows, 16-word segs

    auto load_chunk = [&](int it, int stage) {
        const uint32_t s0 = smb + stage * SWRD * 4;
        const uint32_t* srcA = AH + (size_t)(m0 + arow) * KP + it * 16 + aq;
        uint32_t dA = s0 + (arow * 20 + aq) * 4;
        cpa16(dA,      srcA);
        cpa16(dA + 16, srcA + 4);
        const uint32_t* srcB = Bh + (size_t)(it * 16 + brow) * HW + n0 + bs;
        uint32_t dB = s0 + (1280 + brow * 136 + bs) * 4;
        #pragma unroll
        for (int q = 0; q < 4; q++) cpa16(dB + q * 16, srcB + q * 4);
    };

    load_chunk(0, 0); CPA_COMMIT();
    load_chunk(1, 1); CPA_COMMIT();

    float c[2][8][4] = {};

    for (int it = 0; it < NKIT; it++) {
        if (it + 2 < NKIT) { load_chunk(it + 2, (it + 2) % NSTG); CPA_COMMIT(); CPA_WAIT2(); }
        else if (it + 1 < NKIT) { CPA_WAIT1(); }
        else { CPA_WAIT0(); }
        __syncthreads();

        const uint32_t* sAh = sm + (it % NSTG) * SWRD;
        const uint32_t* sBh = sAh + 1280;

        #pragma unroll
        for (int ks = 0; ks < 2; ks++) {
            const int kp0 = ks * 8;
            uint32_t ah[2][4], bh[8][2];
            #pragma unroll
            for (int mt = 0; mt < 2; mt++) {
                int r = wm * 32 + mt * 16 + g;
                ah[mt][0] = sAh[r * 20 + kp0 + tg];
                ah[mt][1] = sAh[(r + 8) * 20 + kp0 + tg];
                ah[mt][2] = sAh[r * 20 + kp0 + tg + 4];
                ah[mt][3] = sAh[(r + 8) * 20 + kp0 + tg + 4];
            }
            #pragma unroll
            for (int nt = 0; nt < 8; nt++) {
                int col = wn * 64 + nt * 8 + g;
                bh[nt][0] = sBh[(kp0 + tg) * 136 + col];
                bh[nt][1] = sBh[(kp0 + tg + 4) * 136 + col];
            }
            #pragma unroll
            for (int nt = 0; nt < 8; nt++)
                #pragma unroll
                for (int mt = 0; mt < 2; mt++) mma_fp16(c[mt][nt], ah[mt], bh[nt]);
        }
        __syncthreads();
    }

    // ---- epilogue: stage C tile in smem (stride 132), coalesced writeout ----
    float* Cs = (float*)sm;               // 64*132 = 8448 w (fits in 10368)
    #pragma unroll
    for (int mt = 0; mt < 2; mt++)
        #pragma unroll
        for (int nt = 0; nt < 8; nt++) {
            int r   = wm * 32 + mt * 16 + g;
            int col = wn * 64 + nt * 8 + tg * 2;
            Cs[r * 132 + col]           = c[mt][nt][0];
            Cs[r * 132 + col + 1]       = c[mt][nt][1];
            Cs[(r + 8) * 132 + col]     = c[mt][nt][2];
            Cs[(r + 8) * 132 + col + 1] = c[mt][nt][3];
        }
    __syncthreads();

    #pragma unroll 8
    for (int i = tid; i < 8192; i += 128) {
        int r = i >> 7, n = i & 127;
        float v = Cs[r * 132 + n];
        if (MODE == 1) {
            int m = m0 + r;
            float sc = __ldg(&gamma[m]) * rsqrtf(__ldg(&var[m]) + 1e-5f);
            v = v * sc + __ldg(&beta[m]) - __ldg(&mean[m]) * sc;
        }
        Cb[(size_t)(m0 + r) * HW + n0 + n] = v;
    }
}

// ------- fused p-mix + depthwise 3x3 (SAME), 4 output rows per block --------
__global__ void __launch_bounds__(256)
pdw_kernel(const float* __restrict__ QKV,
           const float* __restrict__ Wp,
           const float* __restrict__ Wd,
           float* __restrict__ D)
{
    __shared__ float sin[8][6][WIDTH];    // 24 KB
    __shared__ float sp [8][6][WIDTH];    // 24 KB

    const int b  = blockIdx.z;
    const int gr = blockIdx.y;
    const int h0 = blockIdx.x * 4;        // output rows h0..h0+3
    const int tid = threadIdx.x;
    const float* src = QKV + ((size_t)b * CQKV + gr * 8) * HW;

    // load 8 in-channels x 6 rows (h0-1 .. h0+4, zero-padded)
    #pragma unroll
    for (int i = 0; i < 24; i++) {
        int lin = tid + i * 256;          // 0..6143
        int ch = lin / 768, rem = lin - ch * 768;
        int rs = rem >> 7, col = rem & 127;
        int row = h0 - 1 + rs;
        sin[ch][rs][col] = ((unsigned)row < (unsigned)WIDTH)
                           ? src[ch * HW + row * WIDTH + col] : 0.f;
    }
    __syncthreads();

    // mix: p[o][r][c] = sum_i Wp[gr][o][i] * in[i][r][c]
    #pragma unroll
    for (int i = 0; i < 24; i++) {
        int lin = tid + i * 256;
        int oc = lin / 768, rem = lin - oc * 768;
        int rs = rem >> 7, col = rem & 127;
        float s = 0.f;
        #pragma unroll
        for (int ic = 0; ic < 8; ic++)
            s += __ldg(&Wp[gr * 64 + oc * 8 + ic]) * sin[ic][rs][col];
        sp[oc][rs][col] = s;
    }
    __syncthreads();

    // conv: out[oc][h0+hr][col], taps from sp rows hr..hr+2
    #pragma unroll
    for (int i = 0; i < 16; i++) {
        int lin = tid + i * 256;          // 0..4095
        int oc = lin >> 9, hr = (lin >> 7) & 3, col = lin & 127;
        int c = gr * 8 + oc;
        float s = 0.f;
        #pragma unroll
        for (int ky = 0; ky < 3; ky++) {
            float w0 = __ldg(&Wd[c * 9 + ky * 3 + 0]);
            float w1 = __ldg(&Wd[c * 9 + ky * 3 + 1]);
            float w2 = __ldg(&Wd[c * 9 + ky * 3 + 2]);
            const float* row = sp[oc][hr + ky];
            if (col > 0)   s += w0 * row[col - 1];
            s += w1 * row[col];
            if (col < 127) s += w2 * row[col + 1];
        }
        D[((size_t)b * CQKV + c) * HW + (h0 + hr) * WIDTH + col] = s;
    }
}

// ---------------- kv partial sums (float4 loads, 4 px/thread/row) -----------
__global__ void __launch_bounds__(256)
kv_kernel(const float* __restrict__ QKV,
          const float* __restrict__ D,
          float* __restrict__ kvp)
{
    const int b = blockIdx.z, G = blockIdx.y, chunk = blockIdx.x;
    const int tid = threadIdx.x;
    const float* base = (G < 8) ? QKV + ((size_t)b * CQKV + G * 24) * HW
                                : D   + ((size_t)b * CQKV + (G - 8) * 24) * HW;
    float acc[72];
    #pragma unroll
    for (int i = 0; i < 72; i++) acc[i] = 0.f;

    #pragma unroll
    for (int it = 0; it < 2; it++) {
        int n = chunk * 2048 + it * 1024 + tid * 4;
        float4 kr[8], vr[8];
        #pragma unroll
        for (int d = 0; d < 8; d++) {
            float4 t = *(const float4*)&base[(8 + d) * HW + n];
            kr[d].x = fmaxf(t.x, 0.f); kr[d].y = fmaxf(t.y, 0.f);
            kr[d].z = fmaxf(t.z, 0.f); kr[d].w = fmaxf(t.w, 0.f);
        }
        #pragma unroll
        for (int e = 0; e < 8; e++) vr[e] = *(const float4*)&base[(16 + e) * HW + n];
        #pragma unroll
        for (int d = 0; d < 8; d++) {
            #pragma unroll
            for (int e = 0; e < 8; e++)
                acc[d * 9 + e] += kr[d].x * vr[e].x + kr[d].y * vr[e].y
                                + kr[d].z * vr[e].z + kr[d].w * vr[e].w;
            acc[d * 9 + 8] += kr[d].x + kr[d].y + kr[d].z + kr[d].w;
        }
    }

    __shared__ float red[8][72];
    const int lane = tid & 31, warp = tid >> 5;
    #pragma unroll
    for (int i = 0; i < 72; i++) {
        float v = acc[i];
        #pragma unroll
        for (int off = 16; off; off >>= 1) v += __shfl_down_sync(0xffffffffu, v, off);
        if (lane == 0) red[warp][i] = v;
    }
    __syncthreads();
    for (int i = tid; i < 72; i += 256) {
        float s = 0.f;
        #pragma unroll
        for (int w2 = 0; w2 < 8; w2++) s += red[w2][i];
        kvp[((size_t)(b * 16 + G) * 8 + chunk) * 72 + i] = s;
    }
}

// ------- o = normalize(relu(q)@kv), 4 px/thread, packed fp16 output ---------
// Folds the kvp chunk-reduction (deterministic, per-block in smem).
__global__ void __launch_bounds__(256)
o_kernel(const float* __restrict__ QKV,
         const float* __restrict__ D,
         const float* __restrict__ kvp,
         uint32_t* __restrict__ OH)
{
    const int b = blockIdx.y;
    __shared__ float skv[16 * 72];
    for (int i = threadIdx.x; i < 16 * 72; i += 256) {
        float s = 0.f;
        #pragma unroll
        for (int c = 0; c < 8; c++)
            s += kvp[((size_t)(b * 16 + (i / 72)) * 8 + c) * 72 + (i % 72)];
        skv[i] = s;
    }
    __syncthreads();

    const int n = blockIdx.x * 1024 + threadIdx.x * 4;
    #pragma unroll
    for (int G = 0; G < 16; G++) {
        const float* base = (G < 8) ? QKV + ((size_t)b * CQKV + G * 24) * HW
                                    : D   + ((size_t)b * CQKV + (G - 8) * 24) * HW;
        float4 num[8];
        #pragma unroll
        for (int j = 0; j < 8; j++) num[j] = make_float4(0.f, 0.f, 0.f, 0.f);
        float4 den = make_float4(0.f, 0.f, 0.f, 0.f);
        #pragma unroll
        for (int d = 0; d < 8; d++) {
            float4 t = *(const float4*)&base[d * HW + n];
            float qx = fmaxf(t.x, 0.f), qy = fmaxf(t.y, 0.f);
            float qz = fmaxf(t.z, 0.f), qw = fmaxf(t.w, 0.f);
            #pragma unroll
            for (int j = 0; j < 8; j++) {
                float w = skv[G * 72 + d * 9 + j];
                num[j].x += qx * w; num[j].y += qy * w;
                num[j].z += qz * w; num[j].w += qw * w;
            }
            float w8 = skv[G * 72 + d * 9 + 8];
            den.x += qx * w8; den.y += qy * w8;
            den.z += qz * w8; den.w += qw * w8;
        }
        float invx = 1.f / (den.x + 1e-15f);
        float invy = 1.f / (den.y + 1e-15f);
        float invz = 1.f / (den.z + 1e-15f);
        float invw = 1.f / (den.w + 1e-15f);
        #pragma unroll
        for (int jj = 0; jj < 4; jj++) {
            uint4 w;
            w.x = hpack(num[2 * jj].x * invx, num[2 * jj + 1].x * invx);
            w.y = hpack(num[2 * jj].y * invy, num[2 * jj + 1].y * invy);
            w.z = hpack(num[2 * jj].z * invz, num[2 * jj + 1].z * invz);
            w.w = hpack(num[2 * jj].w * invw, num[2 * jj + 1].w * invw);
            *(uint4*)&OH[((size_t)b * 64 + G * 4 + jj) * HW + n] = w;
        }
    }
}

// ---------------- launch --------------------------------------------------
extern "C" void kernel_launch(void* const* d_in, const int* in_sizes, int n_in,
                              void* d_out, int out_size)
{
    const float* x     = (const float*)d_in[0];
    const float* W_qkv = (const float*)d_in[1];
    const float* W_p   = (const float*)d_in[2];
    const float* W_d   = (const float*)d_in[3];
    const float* W_ffn = (const float*)d_in[4];
    const float* gamma = (const float*)d_in[5];
    const float* beta  = (const float*)d_in[6];
    const float* mean  = (const float*)d_in[7];
    const float* var   = (const float*)d_in[8];
    float* out = (float*)d_out;

    float *qkv, *d, *kvp;
    uint32_t *xh, *oh, *wqh, *wfh;
    cudaGetSymbolAddress((void**)&qkv, g_qkv);
    cudaGetSymbolAddress((void**)&d,   g_d);
    cudaGetSymbolAddress((void**)&xh,  g_xh);
    cudaGetSymbolAddress((void**)&oh,  g_oh);
    cudaGetSymbolAddress((void**)&wqh, g_wqh);
    cudaGetSymbolAddress((void**)&wfh, g_wfh);
    cudaGetSymbolAddress((void**)&kvp, g_kvp);

    // 0) operand conversions (once per call)
    wcvt_kernel<<<(CQKV * 128 + 255) / 256, 256>>>(W_qkv, wqh, CQKV * 128);
    wcvt_kernel<<<(256 * 64 + 255) / 256, 256>>>(W_ffn, wfh, 256 * 64);
    xcvt_kernel<<<NB * 128 * (HW / 4) / 256, 256>>>(x, xh);

    // 1) qkv = W_qkv @ x   (fp16 HMMA, 64x128 block, 3-stage — frozen config)
    hgemm<256, 0><<<dim3(HW / 128, CQKV / 64, NB), 128>>>(
        wqh, xh, qkv, CQKV, nullptr, nullptr, nullptr, nullptr);

    // 2) d = depthwise3x3(blockdiag(W_p) @ qkv)   (4-row strips)
    pdw_kernel<<<dim3(WIDTH / 4, 24, NB), 256>>>(qkv, W_p, W_d, d);

    // 3) kv partial sums (float4 loads)
    kv_kernel<<<dim3(8, 16, NB), 256>>>(qkv, d, kvp);

    // 4) o = normalize(relu(q) @ kv) -> packed fp16 pairs (4 px/thread)
    o_kernel<<<dim3(HW / 1024, NB), 256>>>(qkv, d, kvp, oh);

    // 5) out = BN(W_ffn @ o)   (frozen config)
    hgemm<128, 1><<<dim3(HW / 128, 256 / 64, NB), 128>>>(
        wfh, oh, out, 256, gamma, beta, mean, var);
}

// round 17
// speedup vs baseline: 1.0918x; 1.0645x over previous
#include <cuda_runtime.h>
#include <cuda_fp16.h>
#include <math.h>
#include <stdint.h>

#define HW    16384
#define WIDTH 128
#define NB    8
#define CQKV  192

// ---------------- scratch (static device allocations; no cudaMalloc) --------
__device__ float    g_qkv[NB * CQKV * HW];    // 100.7 MB
__device__ float    g_d  [NB * CQKV * HW];    // 100.7 MB
__device__ uint32_t g_xh [NB * 128 * HW];     // x packed fp16-pair (67 MB)
__device__ uint32_t g_oh [NB * 64 * HW];      // o packed fp16-pair (33.5 MB)
__device__ uint32_t g_wqh[CQKV * 128];        // qkv weights packed
__device__ uint32_t g_wfh[256 * 64];          // ffn weights packed
__device__ float    g_kvp[NB * 16 * 8 * 72];

// ---------------- fp16 helpers ----------------------------------------------
__device__ __forceinline__ uint32_t hpack(float a, float b) {
    __half2 t = __floats2half2_rn(a, b);      // .x = a (low), .y = b (high)
    return *reinterpret_cast<uint32_t*>(&t);
}
__device__ __forceinline__ void mma_fp16(float c[4], const uint32_t a[4], const uint32_t b[2]) {
    asm volatile(
        "mma.sync.aligned.m16n8k16.row.col.f32.f16.f16.f32 "
        "{%0,%1,%2,%3}, {%4,%5,%6,%7}, {%8,%9}, {%0,%1,%2,%3};\n"
        : "+f"(c[0]), "+f"(c[1]), "+f"(c[2]), "+f"(c[3])
        : "r"(a[0]), "r"(a[1]), "r"(a[2]), "r"(a[3]), "r"(b[0]), "r"(b[1]));
}
__device__ __forceinline__ uint32_t smem_u32(const void* p) {
    uint32_t a;
    asm("{ .reg .u64 t; cvta.to.shared.u64 t, %1; cvt.u32.u64 %0, t; }" : "=r"(a) : "l"(p));
    return a;
}
__device__ __forceinline__ void cpa16(uint32_t dst, const void* src) {
    asm volatile("cp.async.cg.shared.global [%0], [%1], 16;\n" :: "r"(dst), "l"(src));
}
#define CPA_COMMIT() asm volatile("cp.async.commit_group;\n" ::: "memory")
#define CPA_WAIT2()  asm volatile("cp.async.wait_group 2;\n" ::: "memory")
#define CPA_WAIT1()  asm volatile("cp.async.wait_group 1;\n" ::: "memory")
#define CPA_WAIT0()  asm volatile("cp.async.wait_group 0;\n" ::: "memory")

// ---------------- convert kernels -------------------------------------------
__global__ void wcvt_kernel(const float* __restrict__ W,
                            uint32_t* __restrict__ WH, int npairs)
{
    int i = blockIdx.x * 256 + threadIdx.x;
    if (i >= npairs) return;
    WH[i] = hpack(W[2 * i], W[2 * i + 1]);
}

// X [b][K][HW] -> packed fp16 k-pair array [b][K/2][HW]
__global__ void xcvt_kernel(const float* __restrict__ X, uint32_t* __restrict__ XH)
{
    int idx = blockIdx.x * 256 + threadIdx.x;
    int n  = (idx & 4095) * 4;
    int t  = idx >> 12;                           // b*128 + kp
    const float4 a = *(const float4*)&X[(size_t)t * 2 * HW + n];
    const float4 b = *(const float4*)&X[(size_t)t * 2 * HW + HW + n];
    uint4 w;
    w.x = hpack(a.x, b.x);
    w.y = hpack(a.y, b.y);
    w.z = hpack(a.z, b.z);
    w.w = hpack(a.w, b.w);
    *(uint4*)&XH[(size_t)t * HW + n] = w;
}

// ============ fp16 single-pass HMMA GEMM, 64x128 block, 32x64 warp tiles ====
// C[b](M x HW) = W(M x KTOT) * X[b](KTOT x HW)
// 128 threads = 4 warps (2x2), k32 chunks, 3-stage cp.async pipeline.
// MODE 0: plain store. MODE 1: batchnorm affine on channel (row).
// (R10/R13/R14-measured best configuration — FROZEN.)
template <int KTOT, int MODE>
__global__ void __launch_bounds__(128)
hgemm(const uint32_t* __restrict__ AH,
      const uint32_t* __restrict__ BHg,
      float* __restrict__ C, int M,
      const float* __restrict__ gamma, const float* __restrict__ beta,
      const float* __restrict__ mean,  const float* __restrict__ var)
{
    constexpr int KP   = KTOT / 2;
    constexpr int NKIT = KTOT / 32;
    constexpr int SWRD = 3456;            // A[64][20]=1280 + B[16][136]=2176
    constexpr int NSTG = 3;

    __shared__ uint32_t sm[NSTG * SWRD];  // 41472 B
    const uint32_t smb = smem_u32(sm);

    const int tid  = threadIdx.x;
    const int lane = tid & 31;
    const int warp = tid >> 5;
    const int wm   = warp >> 1;           // 0..1 -> 32 rows
    const int wn   = warp & 1;            // 0..1 -> 64 cols
    const int g    = lane >> 2;
    const int tg   = lane & 3;

    const int m0 = blockIdx.y * 64;
    const int n0 = blockIdx.x * 128;
    const uint32_t* Bh = BHg + (size_t)blockIdx.z * KP * HW;
    float*          Cb = C   + (size_t)blockIdx.z * M * HW;

    // loader roles
    const int arow = tid >> 1, aq = (tid & 1) * 8;    // A: 64 rows, 8-word halves
    const int brow = tid >> 3, bs = (tid & 7) * 16;   // B: 16 kp-rows, 16-word segs

    auto load_chunk = [&](int it, int stage) {
        const uint32_t s0 = smb + stage * SWRD * 4;
        const uint32_t* srcA = AH + (size_t)(m0 + arow) * KP + it * 16 + aq;
        uint32_t dA = s0 + (arow * 20 + aq) * 4;
        cpa16(dA,      srcA);
        cpa16(dA + 16, srcA + 4);
        const uint32_t* srcB = Bh + (size_t)(it * 16 + brow) * HW + n0 + bs;
        uint32_t dB = s0 + (1280 + brow * 136 + bs) * 4;
        #pragma unroll
        for (int q = 0; q < 4; q++) cpa16(dB + q * 16, srcB + q * 4);
    };

    load_chunk(0, 0); CPA_COMMIT();
    load_chunk(1, 1); CPA_COMMIT();

    float c[2][8][4] = {};

    for (int it = 0; it < NKIT; it++) {
        if (it + 2 < NKIT) { load_chunk(it + 2, (it + 2) % NSTG); CPA_COMMIT(); CPA_WAIT2(); }
        else if (it + 1 < NKIT) { CPA_WAIT1(); }
        else { CPA_WAIT0(); }
        __syncthreads();

        const uint32_t* sAh = sm + (it % NSTG) * SWRD;
        const uint32_t* sBh = sAh + 1280;

        #pragma unroll
        for (int ks = 0; ks < 2; ks++) {
            const int kp0 = ks * 8;
            uint32_t ah[2][4], bh[8][2];
            #pragma unroll
            for (int mt = 0; mt < 2; mt++) {
                int r = wm * 32 + mt * 16 + g;
                ah[mt][0] = sAh[r * 20 + kp0 + tg];
                ah[mt][1] = sAh[(r + 8) * 20 + kp0 + tg];
                ah[mt][2] = sAh[r * 20 + kp0 + tg + 4];
                ah[mt][3] = sAh[(r + 8) * 20 + kp0 + tg + 4];
            }
            #pragma unroll
            for (int nt = 0; nt < 8; nt++) {
                int col = wn * 64 + nt * 8 + g;
                bh[nt][0] = sBh[(kp0 + tg) * 136 + col];
                bh[nt][1] = sBh[(kp0 + tg + 4) * 136 + col];
            }
            #pragma unroll
            for (int nt = 0; nt < 8; nt++)
                #pragma unroll
                for (int mt = 0; mt < 2; mt++) mma_fp16(c[mt][nt], ah[mt], bh[nt]);
        }
        __syncthreads();
    }

    // ---- epilogue: stage C tile in smem (stride 132), coalesced writeout ----
    float* Cs = (float*)sm;               // 64*132 = 8448 w (fits in 10368)
    #pragma unroll
    for (int mt = 0; mt < 2; mt++)
        #pragma unroll
        for (int nt = 0; nt < 8; nt++) {
            int r   = wm * 32 + mt * 16 + g;
            int col = wn * 64 + nt * 8 + tg * 2;
            Cs[r * 132 + col]           = c[mt][nt][0];
            Cs[r * 132 + col + 1]       = c[mt][nt][1];
            Cs[(r + 8) * 132 + col]     = c[mt][nt][2];
            Cs[(r + 8) * 132 + col + 1] = c[mt][nt][3];
        }
    __syncthreads();

    #pragma unroll 8
    for (int i = tid; i < 8192; i += 128) {
        int r = i >> 7, n = i & 127;
        float v = Cs[r * 132 + n];
        if (MODE == 1) {
            int m = m0 + r;
            float sc = __ldg(&gamma[m]) * rsqrtf(__ldg(&var[m]) + 1e-5f);
            v = v * sc + __ldg(&beta[m]) - __ldg(&mean[m]) * sc;
        }
        Cb[(size_t)(m0 + r) * HW + n0 + n] = v;
    }
}

// ------- fused p-mix + depthwise 3x3 (SAME), 4 output rows per block --------
__global__ void __launch_bounds__(256)
pdw_kernel(const float* __restrict__ QKV,
           const float* __restrict__ Wp,
           const float* __restrict__ Wd,
           float* __restrict__ D)
{
    __shared__ float sin[8][6][WIDTH];    // 24 KB
    __shared__ float sp [8][6][WIDTH];    // 24 KB

    const int b  = blockIdx.z;
    const int gr = blockIdx.y;
    const int h0 = blockIdx.x * 4;        // output rows h0..h0+3
    const int tid = threadIdx.x;
    const float* src = QKV + ((size_t)b * CQKV + gr * 8) * HW;

    // load 8 in-channels x 6 rows (h0-1 .. h0+4, zero-padded)
    #pragma unroll
    for (int i = 0; i < 24; i++) {
        int lin = tid + i * 256;          // 0..6143
        int ch = lin / 768, rem = lin - ch * 768;
        int rs = rem >> 7, col = rem & 127;
        int row = h0 - 1 + rs;
        sin[ch][rs][col] = ((unsigned)row < (unsigned)WIDTH)
                           ? src[ch * HW + row * WIDTH + col] : 0.f;
    }
    __syncthreads();

    // mix: p[o][r][c] = sum_i Wp[gr][o][i] * in[i][r][c]
    #pragma unroll
    for (int i = 0; i < 24; i++) {
        int lin = tid + i * 256;
        int oc = lin / 768, rem = lin - oc * 768;
        int rs = rem >> 7, col = rem & 127;
        float s = 0.f;
        #pragma unroll
        for (int ic = 0; ic < 8; ic++)
            s += __ldg(&Wp[gr * 64 + oc * 8 + ic]) * sin[ic][rs][col];
        sp[oc][rs][col] = s;
    }
    __syncthreads();

    // conv: out[oc][h0+hr][col], taps from sp rows hr..hr+2
    #pragma unroll
    for (int i = 0; i < 16; i++) {
        int lin = tid + i * 256;          // 0..4095
        int oc = lin >> 9, hr = (lin >> 7) & 3, col = lin & 127;
        int c = gr * 8 + oc;
        float s = 0.f;
        #pragma unroll
        for (int ky = 0; ky < 3; ky++) {
            float w0 = __ldg(&Wd[c * 9 + ky * 3 + 0]);
            float w1 = __ldg(&Wd[c * 9 + ky * 3 + 1]);
            float w2 = __ldg(&Wd[c * 9 + ky * 3 + 2]);
            const float* row = sp[oc][hr + ky];
            if (col > 0)   s += w0 * row[col - 1];
            s += w1 * row[col];
            if (col < 127) s += w2 * row[col + 1];
        }
        D[((size_t)b * CQKV + c) * HW + (h0 + hr) * WIDTH + col] = s;
    }
}

// ---------------- kv partial sums (float4 loads, 4 px/thread/row) -----------
__global__ void __launch_bounds__(256)
kv_kernel(const float* __restrict__ QKV,
          const float* __restrict__ D,
          float* __restrict__ kvp)
{
    const int b = blockIdx.z, G = blockIdx.y, chunk = blockIdx.x;
    const int tid = threadIdx.x;
    const float* base = (G < 8) ? QKV + ((size_t)b * CQKV + G * 24) * HW
                                : D   + ((size_t)b * CQKV + (G - 8) * 24) * HW;
    float acc[72];
    #pragma unroll
    for (int i = 0; i < 72; i++) acc[i] = 0.f;

    #pragma unroll
    for (int it = 0; it < 2; it++) {
        int n = chunk * 2048 + it * 1024 + tid * 4;
        float4 kr[8], vr[8];
        #pragma unroll
        for (int d = 0; d < 8; d++) {
            float4 t = *(const float4*)&base[(8 + d) * HW + n];
            kr[d].x = fmaxf(t.x, 0.f); kr[d].y = fmaxf(t.y, 0.f);
            kr[d].z = fmaxf(t.z, 0.f); kr[d].w = fmaxf(t.w, 0.f);
        }
        #pragma unroll
        for (int e = 0; e < 8; e++) vr[e] = *(const float4*)&base[(16 + e) * HW + n];
        #pragma unroll
        for (int d = 0; d < 8; d++) {
            #pragma unroll
            for (int e = 0; e < 8; e++)
                acc[d * 9 + e] += kr[d].x * vr[e].x + kr[d].y * vr[e].y
                                + kr[d].z * vr[e].z + kr[d].w * vr[e].w;
            acc[d * 9 + 8] += kr[d].x + kr[d].y + kr[d].z + kr[d].w;
        }
    }

    __shared__ float red[8][72];
    const int lane = tid & 31, warp = tid >> 5;
    #pragma unroll
    for (int i = 0; i < 72; i++) {
        float v = acc[i];
        #pragma unroll
        for (int off = 16; off; off >>= 1) v += __shfl_down_sync(0xffffffffu, v, off);
        if (lane == 0) red[warp][i] = v;
    }
    __syncthreads();
    for (int i = tid; i < 72; i += 256) {
        float s = 0.f;
        #pragma unroll
        for (int w2 = 0; w2 < 8; w2++) s += red[w2][i];
        kvp[((size_t)(b * 16 + G) * 8 + chunk) * 72 + i] = s;
    }
}

// ------- o = normalize(relu(q)@kv), 2 px/thread, 4 groups per block ---------
// Grid: (HW/512, 4, NB) = 1024 CTAs -> SMs saturated.
// Folds the kvp chunk-reduction for this block's 4 groups.
__global__ void __launch_bounds__(256)
o_kernel(const float* __restrict__ QKV,
         const float* __restrict__ D,
         const float* __restrict__ kvp,
         uint32_t* __restrict__ OH)
{
    const int b  = blockIdx.z;
    const int G0 = blockIdx.y * 4;        // this block's group range [G0, G0+4)
    __shared__ float skv[4 * 72];
    for (int i = threadIdx.x; i < 4 * 72; i += 256) {
        int G = G0 + i / 72, j = i % 72;
        float s = 0.f;
        #pragma unroll
        for (int c = 0; c < 8; c++)
            s += kvp[((size_t)(b * 16 + G) * 8 + c) * 72 + j];
        skv[i] = s;
    }
    __syncthreads();

    const int n = blockIdx.x * 512 + threadIdx.x * 2;
    #pragma unroll
    for (int Gl = 0; Gl < 4; Gl++) {
        const int G = G0 + Gl;
        const float* base = (G < 8) ? QKV + ((size_t)b * CQKV + G * 24) * HW
                                    : D   + ((size_t)b * CQKV + (G - 8) * 24) * HW;
        float2 num[8];
        #pragma unroll
        for (int j = 0; j < 8; j++) num[j] = make_float2(0.f, 0.f);
        float2 den = make_float2(0.f, 0.f);
        #pragma unroll
        for (int d = 0; d < 8; d++) {
            float2 t = *(const float2*)&base[d * HW + n];
            float qx = fmaxf(t.x, 0.f), qy = fmaxf(t.y, 0.f);
            #pragma unroll
            for (int j = 0; j < 8; j++) {
                float w = skv[Gl * 72 + d * 9 + j];
                num[j].x += qx * w;
                num[j].y += qy * w;
            }
            float w8 = skv[Gl * 72 + d * 9 + 8];
            den.x += qx * w8;
            den.y += qy * w8;
        }
        float invx = 1.f / (den.x + 1e-15f);
        float invy = 1.f / (den.y + 1e-15f);
        #pragma unroll
        for (int jj = 0; jj < 4; jj++) {
            uint2 w;
            w.x = hpack(num[2 * jj].x * invx, num[2 * jj + 1].x * invx);
            w.y = hpack(num[2 * jj].y * invy, num[2 * jj + 1].y * invy);
            *(uint2*)&OH[((size_t)b * 64 + G * 4 + jj) * HW + n] = w;
        }
    }
}

// ---------------- launch --------------------------------------------------
extern "C" void kernel_launch(void* const* d_in, const int* in_sizes, int n_in,
                              void* d_out, int out_size)
{
    const float* x     = (const float*)d_in[0];
    const float* W_qkv = (const float*)d_in[1];
    const float* W_p   = (const float*)d_in[2];
    const float* W_d   = (const float*)d_in[3];
    const float* W_ffn = (const float*)d_in[4];
    const float* gamma = (const float*)d_in[5];
    const float* beta  = (const float*)d_in[6];
    const float* mean  = (const float*)d_in[7];
    const float* var   = (const float*)d_in[8];
    float* out = (float*)d_out;

    float *qkv, *d, *kvp;
    uint32_t *xh, *oh, *wqh, *wfh;
    cudaGetSymbolAddress((void**)&qkv, g_qkv);
    cudaGetSymbolAddress((void**)&d,   g_d);
    cudaGetSymbolAddress((void**)&xh,  g_xh);
    cudaGetSymbolAddress((void**)&oh,  g_oh);
    cudaGetSymbolAddress((void**)&wqh, g_wqh);
    cudaGetSymbolAddress((void**)&wfh, g_wfh);
    cudaGetSymbolAddress((void**)&kvp, g_kvp);

    // 0) operand conversions (once per call)
    wcvt_kernel<<<(CQKV * 128 + 255) / 256, 256>>>(W_qkv, wqh, CQKV * 128);
    wcvt_kernel<<<(256 * 64 + 255) / 256, 256>>>(W_ffn, wfh, 256 * 64);
    xcvt_kernel<<<NB * 128 * (HW / 4) / 256, 256>>>(x, xh);

    // 1) qkv = W_qkv @ x   (fp16 HMMA, 64x128 block, 3-stage — frozen config)
    hgemm<256, 0><<<dim3(HW / 128, CQKV / 64, NB), 128>>>(
        wqh, xh, qkv, CQKV, nullptr, nullptr, nullptr, nullptr);

    // 2) d = depthwise3x3(blockdiag(W_p) @ qkv)   (4-row strips)
    pdw_kernel<<<dim3(WIDTH / 4, 24, NB), 256>>>(qkv, W_p, W_d, d);

    // 3) kv partial sums (float4 loads)
    kv_kernel<<<dim3(8, 16, NB), 256>>>(qkv, d, kvp);

    // 4) o = normalize(relu(q) @ kv) -> packed fp16 pairs (2 px/thread, G-split)
    o_kernel<<<dim3(HW / 512, 4, NB), 256>>>(qkv, d, kvp, oh);

    // 5) out = BN(W_ffn @ o)   (frozen config)
    hgemm<128, 1><<<dim3(HW / 128, 256 / 64, NB), 128>>>(
        wfh, oh, out, 256, gamma, beta, mean, var);
}